// round 16
// baseline (speedup 1.0000x reference)
#include <cuda_runtime.h>
#include <cuda_fp16.h>
#include <math.h>
#include <cstdint>
#include <string.h>

#define HID     2048
#define NHEADS  16
#define HDIM    128
#define BATCHSZ 2
#define SEQLEN  2048
#define MTOT    (BATCHSZ * SEQLEN)   // 4096

// ---------------- scratch (allocation-free), single fp16 -------------------
__device__ __half g_xh [MTOT * HID];
__device__ __half g_wh [4 * HID * HID];
__device__ __half g_qh [MTOT * HID];     // Q (prescaled by 1/sqrt(d))
__device__ __half g_kh [MTOT * HID];
__device__ __half g_vh [MTOT * HID];
__device__ __half g_oh [MTOT * HID];     // attention output

// ============================ helpers ======================================
__device__ __forceinline__ uint32_t smem_u32(const void* p) {
    uint32_t a;
    asm("{ .reg .u64 t; cvta.to.shared.u64 t, %1; cvt.u32.u64 %0, t; }"
        : "=r"(a) : "l"(p));
    return a;
}

#define LDSM_X4(r0, r1, r2, r3, addr)                                    \
    asm volatile("ldmatrix.sync.aligned.m8n8.x4.shared.b16 "             \
                 "{%0,%1,%2,%3}, [%4];"                                  \
                 : "=r"(r0), "=r"(r1), "=r"(r2), "=r"(r3) : "r"(addr))

#define LDSM_X4_T(r0, r1, r2, r3, addr)                                  \
    asm volatile("ldmatrix.sync.aligned.m8n8.x4.trans.shared.b16 "       \
                 "{%0,%1,%2,%3}, [%4];"                                  \
                 : "=r"(r0), "=r"(r1), "=r"(r2), "=r"(r3) : "r"(addr))

#define MMA_F16(c0, c1, c2, c3, a0, a1, a2, a3, b0, b1)                  \
    asm volatile("mma.sync.aligned.m16n8k16.row.col.f32.f16.f16.f32 "    \
                 "{%0,%1,%2,%3}, {%4,%5,%6,%7}, {%8,%9}, {%0,%1,%2,%3};" \
                 : "+f"(c0), "+f"(c1), "+f"(c2), "+f"(c3)                \
                 : "r"(a0), "r"(a1), "r"(a2), "r"(a3), "r"(b0), "r"(b1))

#define CP16(saddr, gptr)                                                \
    asm volatile("cp.async.cg.shared.global [%0], [%1], 16;"             \
                 :: "r"(saddr), "l"(gptr))
#define CP_COMMIT() asm volatile("cp.async.commit_group;" ::: "memory")
#define CP_WAIT0()  asm volatile("cp.async.wait_group 0;" ::: "memory")

__device__ __forceinline__ uint32_t pack_f16(float a, float b) {
    __half2 h = __floats2half2_rn(a, b);
    uint32_t u; memcpy(&u, &h, 4);
    return u;
}

// ======================= fused prep kernel (one launch) ====================
__global__ __launch_bounds__(256)
void prep_kernel(const float* __restrict__ x,
                 const float* __restrict__ wq, const float* __restrict__ wk,
                 const float* __restrict__ wv, const float* __restrict__ wo) {
    const int z = blockIdx.y;
    const int i = (blockIdx.x * 256 + threadIdx.x) * 4;
    if (z == 0) {
        if (i >= MTOT * HID) return;
        float4 v = *(const float4*)(x + i);
        *(__half2*)(g_xh + i)     = __floats2half2_rn(v.x, v.y);
        *(__half2*)(g_xh + i + 2) = __floats2half2_rn(v.z, v.w);
    } else {
        const int nw = HID * HID;
        if (i >= nw) return;
        const float* src = (z == 1) ? wq : (z == 2) ? wk : (z == 3) ? wv : wo;
        __half* hi = g_wh + (size_t)(z - 1) * nw;
        float4 v = *(const float4*)(src + i);
        *(__half2*)(hi + i)     = __floats2half2_rn(v.x, v.y);
        *(__half2*)(hi + i + 2) = __floats2half2_rn(v.z, v.w);
    }
}

// ============ pipelined fp16 single-term GEMM (cp.async, 2-stage) ==========
#define KSTRIDE 40
#define TILE_B  (128 * KSTRIDE * 2)      // 10240 B
#define STAGE_B (2 * TILE_B)             // 20480 B
#define GSM_TOTAL (2 * STAGE_B)          // 40960 B
#define NKC (HID / 32)                   // 64

template <int MODE>
__device__ __forceinline__ void gemm_body(const __half* __restrict__ A,
                                          const __half* __restrict__ W,
                                          const float* __restrict__ Bias,
                                          float* __restrict__ OutF,
                                          __half* __restrict__ OutH,
                                          float scale) {
    extern __shared__ char sm[];
    const uint32_t sb = smem_u32(sm);
    const int tid  = threadIdx.x;
    const int wid  = tid >> 5;
    const int lane = tid & 31;
    const int m0 = blockIdx.y * 128;
    const int n0 = blockIdx.x * 128;
    const int wm = wid & 1;
    const int wn = wid >> 1;

    const int lrow = (lane & 7) + ((lane >> 3) & 1) * 8;
    const int lk   = (lane >> 4) * 8;

    const int r0 = tid >> 2;                 // 0..63
    const int c0 = (tid & 3) * 8;
    const __half* gA[2];
    gA[0] = A + (size_t)(m0 + r0) * HID + c0;
    gA[1] = W + (size_t)(n0 + r0) * HID + c0;
    const uint32_t sA0 = sb + (uint32_t)(r0 * 80 + (tid & 3) * 16);
    const uint32_t sA1 = sA0 + 64 * 80;

    float acc[4][4][4];
#pragma unroll
    for (int i = 0; i < 4; i++)
#pragma unroll
        for (int j = 0; j < 4; j++)
#pragma unroll
            for (int c = 0; c < 4; c++) acc[i][j][c] = 0.f;

#pragma unroll
    for (int t = 0; t < 2; t++) {
        CP16(sA0 + t * TILE_B, gA[t]);
        CP16(sA1 + t * TILE_B, gA[t] + (size_t)64 * HID);
    }
    CP_COMMIT();

    for (int kc = 0; kc < NKC; kc++) {
        CP_WAIT0();
        __syncthreads();
        if (kc + 1 < NKC) {
            const uint32_t soff = ((kc + 1) & 1) * STAGE_B;
            const int go = (kc + 1) * 32;
#pragma unroll
            for (int t = 0; t < 2; t++) {
                CP16(sA0 + soff + t * TILE_B, gA[t] + go);
                CP16(sA1 + soff + t * TILE_B, gA[t] + (size_t)64 * HID + go);
            }
            CP_COMMIT();
        }

        const uint32_t stg = (kc & 1) * STAGE_B;
        const uint32_t aH = sb + stg + (uint32_t)(((wm * 64 + lrow) * KSTRIDE + lk) * 2);
        const uint32_t bH = sb + stg + TILE_B +
                            (uint32_t)(((wn * 32 + lrow) * KSTRIDE + lk) * 2);
#pragma unroll
        for (int ks = 0; ks < 2; ks++) {
            const uint32_t ko = (uint32_t)(ks * 32);
            uint32_t bh[4][2];
#pragma unroll
            for (int p = 0; p < 2; p++) {
                const uint32_t ba = bH + (uint32_t)(p * 16 * KSTRIDE * 2) + ko;
                uint32_t q0, q1, q2, q3;
                LDSM_X4(q0, q1, q2, q3, ba);
                bh[2 * p][0] = q0; bh[2 * p][1] = q2;
                bh[2 * p + 1][0] = q1; bh[2 * p + 1][1] = q3;
            }
#pragma unroll
            for (int mf = 0; mf < 4; mf++) {
                const uint32_t aa = aH + (uint32_t)(mf * 16 * KSTRIDE * 2) + ko;
                uint32_t a0, a1, a2, a3;
                LDSM_X4(a0, a1, a2, a3, aa);
#pragma unroll
                for (int nf = 0; nf < 4; nf++)
                    MMA_F16(acc[mf][nf][0], acc[mf][nf][1], acc[mf][nf][2], acc[mf][nf][3],
                            a0, a1, a2, a3, bh[nf][0], bh[nf][1]);
            }
        }
    }

    // ---- epilogue ----
    const int g = lane >> 2;
    const int t = lane & 3;
#pragma unroll
    for (int mf = 0; mf < 4; mf++) {
#pragma unroll
        for (int nf = 0; nf < 4; nf++) {
            const int m_lo = m0 + wm * 64 + mf * 16 + g;
            const int n    = n0 + wn * 32 + nf * 8 + t * 2;
            const float2 bb = *(const float2*)(Bias + n);
            float2 v0, v1;
            v0.x = acc[mf][nf][0] + bb.x; v0.y = acc[mf][nf][1] + bb.y;
            v1.x = acc[mf][nf][2] + bb.x; v1.y = acc[mf][nf][3] + bb.y;
            if (MODE == 0) {
                *(float2*)(OutF + (size_t)m_lo * HID + n)       = v0;
                *(float2*)(OutF + (size_t)(m_lo + 8) * HID + n) = v1;
            } else {
                v0.x *= scale; v0.y *= scale; v1.x *= scale; v1.y *= scale;
                const int h = n >> 7;
                const int d = n & (HDIM - 1);
                const int b0b = m_lo >> 11, s0 = m_lo & (SEQLEN - 1);
                const int b1b = (m_lo + 8) >> 11, s1 = (m_lo + 8) & (SEQLEN - 1);
                const size_t o0 = ((size_t)(b0b * NHEADS + h) * SEQLEN + s0) * HDIM + d;
                const size_t o1 = ((size_t)(b1b * NHEADS + h) * SEQLEN + s1) * HDIM + d;
                *(__half2*)(OutH + o0) = __floats2half2_rn(v0.x, v0.y);
                *(__half2*)(OutH + o1) = __floats2half2_rn(v1.x, v1.y);
            }
        }
    }
}

__global__ __launch_bounds__(256)
void gemm_qkv_kernel(const float* __restrict__ bq, const float* __restrict__ bk,
                     const float* __restrict__ bv) {
    const int z = blockIdx.z;
    const __half* W = g_wh + (size_t)z * HID * HID;
    const float* B = (z == 0) ? bq : (z == 1 ? bk : bv);
    __half* O = (z == 0) ? g_qh : (z == 1 ? g_kh : g_vh);
    const float scale = (z == 0) ? 0.08838834764831845f : 1.0f;
    gemm_body<1>(g_xh, W, B, nullptr, O, scale);
}

__global__ __launch_bounds__(256)
void gemm_out_kernel(const float* __restrict__ bo, float* __restrict__ out) {
    gemm_body<0>(g_oh, g_wh + (size_t)3 * HID * HID, bo, out, nullptr, 1.0f);
}

// ============== Flash attention (fp16, double-buffered K/V, 2 CTA/SM) ======
// CTA = 128 q-rows of one (b,h); kv tile 64. 2-stage cp.async K/V.
// Smem 104448 B x 2 CTAs = 208896 <= 228KB; regs capped 128 (frame ~115).
#define AQ 136
#define AT_QH 0
#define AT_KV0 34816
#define KV_STG 34816
#define KV_VH  17408
#define AT_SMEM (AT_KV0 + 2 * KV_STG)    // 104448

__global__ __launch_bounds__(256, 2)
void attn_mma_kernel() {
    extern __shared__ char sm[];
    const uint32_t sb = smem_u32(sm);
    const int tid  = threadIdx.x;
    const int wid  = tid >> 5;
    const int lane = tid & 31;
    const int qt = blockIdx.x;
    const int bh = blockIdx.y;
    const int q0 = qt * 128;

    const size_t base = (size_t)bh * SEQLEN * HDIM;

    const int lrow = (lane & 7) + ((lane >> 3) & 1) * 8;
    const int lk   = (lane >> 4) * 8;
    const int g    = lane >> 2;
    const int t    = lane & 3;

    // KV loader: row = tid>>2 (0..63), 16B chunks at (tid&3)*4..+3
    const int krow = tid >> 2;
    const int kchk = (tid & 3) * 4;
    const uint32_t kvd = sb + AT_KV0 + (uint32_t)(krow * (AQ * 2) + kchk * 16);
    const size_t   kvs = base + (size_t)krow * HDIM + kchk * 8;

    // ---- load Q tile (pure copy) ----
    {
        const int row  = tid >> 1;
        const int half = (tid & 1) * 64;
        const __half* qh = g_qh + base + (size_t)(q0 + row) * HDIM + half;
        char* dh = sm + AT_QH + (row * AQ + half) * 2;
#pragma unroll
        for (int c = 0; c < 8; c++)
            *(uint4*)(dh + c * 16) = *(const uint4*)(qh + c * 8);
    }

    // ---- prologue: prefetch KV tile 0 into stage 0 ----
#pragma unroll
    for (int c = 0; c < 4; c++) {
        CP16(kvd + c * 16,          g_kh + kvs + c * 8);
        CP16(kvd + KV_VH + c * 16,  g_vh + kvs + c * 8);
    }
    CP_COMMIT();

    float mi0 = -INFINITY, mi1 = -INFINITY, li0 = 0.f, li1 = 0.f;
    float o[16][4];
#pragma unroll
    for (int nf = 0; nf < 16; nf++)
#pragma unroll
        for (int c = 0; c < 4; c++) o[nf][c] = 0.f;

    const int qrow0 = q0 + wid * 16 + g;
    const int qrow1 = qrow0 + 8;
    const int jmax  = 2 * qt + 2;

    const uint32_t aQ  = sb + AT_QH + (uint32_t)(((wid * 16 + lrow) * AQ + lk) * 2);
    const uint32_t bK0 = sb + AT_KV0 + (uint32_t)((lrow * AQ + lk) * 2);
    const uint32_t bV0 = sb + AT_KV0 + KV_VH +
        (uint32_t)((((lane & 7) + ((lane >> 3) & 1) * 8) * AQ + ((lane >> 4) & 1) * 8) * 2);

    for (int j = 0; j < jmax; j++) {
        CP_WAIT0();
        __syncthreads();

        // ---- prefetch KV tile j+1 into alternate stage ----
        if (j + 1 < jmax) {
            const uint32_t so = ((j + 1) & 1) * KV_STG;
            const size_t  gso = kvs + (size_t)(j + 1) * 64 * HDIM;
#pragma unroll
            for (int c = 0; c < 4; c++) {
                CP16(kvd + so + c * 16,         g_kh + gso + c * 8);
                CP16(kvd + so + KV_VH + c * 16, g_vh + gso + c * 8);
            }
            CP_COMMIT();
        }

        const int k0 = j * 64;
        const uint32_t stg = (j & 1) * KV_STG;
        const uint32_t bKh = bK0 + stg;
        const uint32_t bVt = bV0 + stg;

        // ---- S = Q @ K^T ----
        float s[8][4];
#pragma unroll
        for (int nf = 0; nf < 8; nf++)
#pragma unroll
            for (int c = 0; c < 4; c++) s[nf][c] = 0.f;

#pragma unroll
        for (int ks = 0; ks < 8; ks++) {
            const uint32_t ko = (uint32_t)(ks * 32);
            uint32_t q0r, q1r, q2r, q3r;
            LDSM_X4(q0r, q1r, q2r, q3r, aQ + ko);
#pragma unroll
            for (int p = 0; p < 4; p++) {
                const uint32_t po = (uint32_t)(p * 16 * AQ * 2) + ko;
                uint32_t kh0, kh1, kh2, kh3;
                LDSM_X4(kh0, kh1, kh2, kh3, bKh + po);
                MMA_F16(s[2*p][0], s[2*p][1], s[2*p][2], s[2*p][3],
                        q0r, q1r, q2r, q3r, kh0, kh2);
                MMA_F16(s[2*p+1][0], s[2*p+1][1], s[2*p+1][2], s[2*p+1][3],
                        q0r, q1r, q2r, q3r, kh1, kh3);
            }
        }

        // ---- causal mask ----
        if (j >= 2 * qt) {
#pragma unroll
            for (int nf = 0; nf < 8; nf++) {
                const int kc = k0 + nf * 8 + t * 2;
                if (kc     > qrow0) s[nf][0] = -INFINITY;
                if (kc + 1 > qrow0) s[nf][1] = -INFINITY;
                if (kc     > qrow1) s[nf][2] = -INFINITY;
                if (kc + 1 > qrow1) s[nf][3] = -INFINITY;
            }
        }

        // ---- online softmax + pack P (fp16) ----
        float rmax0 = -INFINITY, rmax1 = -INFINITY;
#pragma unroll
        for (int nf = 0; nf < 8; nf++) {
            rmax0 = fmaxf(rmax0, fmaxf(s[nf][0], s[nf][1]));
            rmax1 = fmaxf(rmax1, fmaxf(s[nf][2], s[nf][3]));
        }
        rmax0 = fmaxf(rmax0, __shfl_xor_sync(0xffffffffu, rmax0, 1));
        rmax0 = fmaxf(rmax0, __shfl_xor_sync(0xffffffffu, rmax0, 2));
        rmax1 = fmaxf(rmax1, __shfl_xor_sync(0xffffffffu, rmax1, 1));
        rmax1 = fmaxf(rmax1, __shfl_xor_sync(0xffffffffu, rmax1, 2));
        const float mn0 = fmaxf(mi0, rmax0);
        const float mn1 = fmaxf(mi1, rmax1);
        const float corr0 = __expf(mi0 - mn0);
        const float corr1 = __expf(mi1 - mn1);
        mi0 = mn0; mi1 = mn1;

        uint32_t ph[4][4];
        float rs0 = 0.f, rs1 = 0.f;
#pragma unroll
        for (int nf = 0; nf < 8; nf++) {
            const float p0 = __expf(s[nf][0] - mn0);
            const float p1 = __expf(s[nf][1] - mn0);
            const float p2 = __expf(s[nf][2] - mn1);
            const float p3 = __expf(s[nf][3] - mn1);
            rs0 += p0 + p1;
            rs1 += p2 + p3;
            const int ks = nf >> 1;
            const int r  = (nf & 1) * 2;
            ph[ks][r]     = pack_f16(p0, p1);
            ph[ks][r + 1] = pack_f16(p2, p3);
        }
        rs0 += __shfl_xor_sync(0xffffffffu, rs0, 1);
        rs0 += __shfl_xor_sync(0xffffffffu, rs0, 2);
        rs1 += __shfl_xor_sync(0xffffffffu, rs1, 1);
        rs1 += __shfl_xor_sync(0xffffffffu, rs1, 2);
        li0 = li0 * corr0 + rs0;
        li1 = li1 * corr1 + rs1;

#pragma unroll
        for (int nf = 0; nf < 16; nf++) {
            o[nf][0] *= corr0; o[nf][1] *= corr0;
            o[nf][2] *= corr1; o[nf][3] *= corr1;
        }

        // ---- O += P @ V (V via ldmatrix.trans) ----
#pragma unroll
        for (int ks = 0; ks < 4; ks++) {
            const uint32_t kvo = (uint32_t)(ks * 16 * AQ * 2);
#pragma unroll
            for (int p = 0; p < 8; p++) {
                const uint32_t va = bVt + kvo + (uint32_t)(p * 16 * 2);
                uint32_t vh0, vh1, vh2, vh3;
                LDSM_X4_T(vh0, vh1, vh2, vh3, va);
                MMA_F16(o[2*p][0], o[2*p][1], o[2*p][2], o[2*p][3],
                        ph[ks][0], ph[ks][1], ph[ks][2], ph[ks][3], vh0, vh1);
                MMA_F16(o[2*p+1][0], o[2*p+1][1], o[2*p+1][2], o[2*p+1][3],
                        ph[ks][0], ph[ks][1], ph[ks][2], ph[ks][3], vh2, vh3);
            }
        }
    }

    // ---- normalize + write fp16 attn output ----
    const int b = bh >> 4, h = bh & 15;
    const float inv0 = 1.0f / li0;
    const float inv1 = 1.0f / li1;
    const size_t r0base = ((size_t)b * SEQLEN + qrow0) * HID + h * HDIM;
    const size_t r1base = ((size_t)b * SEQLEN + qrow1) * HID + h * HDIM;
#pragma unroll
    for (int nf = 0; nf < 16; nf++) {
        const int d = nf * 8 + t * 2;
        *(__half2*)(g_oh + r0base + d) = __floats2half2_rn(o[nf][0] * inv0, o[nf][1] * inv0);
        *(__half2*)(g_oh + r1base + d) = __floats2half2_rn(o[nf][2] * inv1, o[nf][3] * inv1);
    }
}

// ---------------------------------------------------------------------------
extern "C" void kernel_launch(void* const* d_in, const int* in_sizes, int n_in,
                              void* d_out, int out_size) {
    const float* x  = (const float*)d_in[0];
    const float* wq = (const float*)d_in[1];
    const float* wk = (const float*)d_in[2];
    const float* wv = (const float*)d_in[3];
    const float* wo = (const float*)d_in[4];
    const float* bq = (const float*)d_in[5];
    const float* bk = (const float*)d_in[6];
    const float* bv = (const float*)d_in[7];
    const float* bo = (const float*)d_in[8];
    float* out = (float*)d_out;

    cudaFuncSetAttribute(gemm_qkv_kernel,
                         cudaFuncAttributeMaxDynamicSharedMemorySize, GSM_TOTAL);
    cudaFuncSetAttribute(gemm_out_kernel,
                         cudaFuncAttributeMaxDynamicSharedMemorySize, GSM_TOTAL);
    cudaFuncSetAttribute(attn_mma_kernel,
                         cudaFuncAttributeMaxDynamicSharedMemorySize, AT_SMEM);

    // 0) fused one-time fp16 rounding (x + 4 weights)
    prep_kernel<<<dim3(MTOT * HID / 1024, 5), 256>>>(x, wq, wk, wv, wo);

    // 1) QKV projections (single-term fp16 GEMM)
    gemm_qkv_kernel<<<dim3(HID / 128, MTOT / 128, 3), 256, GSM_TOTAL>>>(bq, bk, bv);
    // 2) Causal flash attention (fp16, double-buffered K/V, 2 CTAs/SM)
    attn_mma_kernel<<<dim3(SEQLEN / 128, BATCHSZ * NHEADS), 256, AT_SMEM>>>();
    // 3) Output projection
    gemm_out_kernel<<<dim3(HID / 128, MTOT / 128), 256, GSM_TOTAL>>>(bo, out);
}

// round 17
// speedup vs baseline: 1.0670x; 1.0670x over previous
#include <cuda_runtime.h>
#include <cuda_fp16.h>
#include <math.h>
#include <cstdint>
#include <string.h>

#define HID     2048
#define NHEADS  16
#define HDIM    128
#define BATCHSZ 2
#define SEQLEN  2048
#define MTOT    (BATCHSZ * SEQLEN)   // 4096

// ---------------- scratch (allocation-free), single fp16 -------------------
__device__ __half g_xh [MTOT * HID];
__device__ __half g_wh [4 * HID * HID];
__device__ __half g_qh [MTOT * HID];     // Q (prescaled by 1/sqrt(d))
__device__ __half g_kh [MTOT * HID];
__device__ __half g_vh [MTOT * HID];
__device__ __half g_oh [MTOT * HID];     // attention output

// ============================ helpers ======================================
__device__ __forceinline__ uint32_t smem_u32(const void* p) {
    uint32_t a;
    asm("{ .reg .u64 t; cvta.to.shared.u64 t, %1; cvt.u32.u64 %0, t; }"
        : "=r"(a) : "l"(p));
    return a;
}

#define LDSM_X4(r0, r1, r2, r3, addr)                                    \
    asm volatile("ldmatrix.sync.aligned.m8n8.x4.shared.b16 "             \
                 "{%0,%1,%2,%3}, [%4];"                                  \
                 : "=r"(r0), "=r"(r1), "=r"(r2), "=r"(r3) : "r"(addr))

#define LDSM_X4_T(r0, r1, r2, r3, addr)                                  \
    asm volatile("ldmatrix.sync.aligned.m8n8.x4.trans.shared.b16 "       \
                 "{%0,%1,%2,%3}, [%4];"                                  \
                 : "=r"(r0), "=r"(r1), "=r"(r2), "=r"(r3) : "r"(addr))

#define MMA_F16(c0, c1, c2, c3, a0, a1, a2, a3, b0, b1)                  \
    asm volatile("mma.sync.aligned.m16n8k16.row.col.f32.f16.f16.f32 "    \
                 "{%0,%1,%2,%3}, {%4,%5,%6,%7}, {%8,%9}, {%0,%1,%2,%3};" \
                 : "+f"(c0), "+f"(c1), "+f"(c2), "+f"(c3)                \
                 : "r"(a0), "r"(a1), "r"(a2), "r"(a3), "r"(b0), "r"(b1))

#define CP16(saddr, gptr)                                                \
    asm volatile("cp.async.cg.shared.global [%0], [%1], 16;"             \
                 :: "r"(saddr), "l"(gptr))
#define CP_COMMIT() asm volatile("cp.async.commit_group;" ::: "memory")
#define CP_WAIT0()  asm volatile("cp.async.wait_group 0;" ::: "memory")

__device__ __forceinline__ uint32_t pack_f16(float a, float b) {
    __half2 h = __floats2half2_rn(a, b);
    uint32_t u; memcpy(&u, &h, 4);
    return u;
}

// ======================= fused prep kernel (one launch) ====================
__global__ __launch_bounds__(256)
void prep_kernel(const float* __restrict__ x,
                 const float* __restrict__ wq, const float* __restrict__ wk,
                 const float* __restrict__ wv, const float* __restrict__ wo) {
    const int z = blockIdx.y;
    const int i = (blockIdx.x * 256 + threadIdx.x) * 4;
    if (z == 0) {
        if (i >= MTOT * HID) return;
        float4 v = *(const float4*)(x + i);
        *(__half2*)(g_xh + i)     = __floats2half2_rn(v.x, v.y);
        *(__half2*)(g_xh + i + 2) = __floats2half2_rn(v.z, v.w);
    } else {
        const int nw = HID * HID;
        if (i >= nw) return;
        const float* src = (z == 1) ? wq : (z == 2) ? wk : (z == 3) ? wv : wo;
        __half* hi = g_wh + (size_t)(z - 1) * nw;
        float4 v = *(const float4*)(src + i);
        *(__half2*)(hi + i)     = __floats2half2_rn(v.x, v.y);
        *(__half2*)(hi + i + 2) = __floats2half2_rn(v.z, v.w);
    }
}

// ============ pipelined fp16 single-term GEMM (cp.async, 2-stage) ==========
// NOW 2 CTAs/SM: regs 114*512=58.4k <= 64k, smem 2x40KB <= carveout.
#define KSTRIDE 40
#define TILE_B  (128 * KSTRIDE * 2)      // 10240 B
#define STAGE_B (2 * TILE_B)             // 20480 B
#define GSM_TOTAL (2 * STAGE_B)          // 40960 B
#define NKC (HID / 32)                   // 64

template <int MODE>
__device__ __forceinline__ void gemm_body(const __half* __restrict__ A,
                                          const __half* __restrict__ W,
                                          const float* __restrict__ Bias,
                                          float* __restrict__ OutF,
                                          __half* __restrict__ OutH,
                                          float scale) {
    extern __shared__ char sm[];
    const uint32_t sb = smem_u32(sm);
    const int tid  = threadIdx.x;
    const int wid  = tid >> 5;
    const int lane = tid & 31;
    const int m0 = blockIdx.y * 128;
    const int n0 = blockIdx.x * 128;
    const int wm = wid & 1;
    const int wn = wid >> 1;

    const int lrow = (lane & 7) + ((lane >> 3) & 1) * 8;
    const int lk   = (lane >> 4) * 8;

    const int r0 = tid >> 2;                 // 0..63
    const int c0 = (tid & 3) * 8;
    const __half* gA[2];
    gA[0] = A + (size_t)(m0 + r0) * HID + c0;
    gA[1] = W + (size_t)(n0 + r0) * HID + c0;
    const uint32_t sA0 = sb + (uint32_t)(r0 * 80 + (tid & 3) * 16);
    const uint32_t sA1 = sA0 + 64 * 80;

    float acc[4][4][4];
#pragma unroll
    for (int i = 0; i < 4; i++)
#pragma unroll
        for (int j = 0; j < 4; j++)
#pragma unroll
            for (int c = 0; c < 4; c++) acc[i][j][c] = 0.f;

#pragma unroll
    for (int t = 0; t < 2; t++) {
        CP16(sA0 + t * TILE_B, gA[t]);
        CP16(sA1 + t * TILE_B, gA[t] + (size_t)64 * HID);
    }
    CP_COMMIT();

    for (int kc = 0; kc < NKC; kc++) {
        CP_WAIT0();
        __syncthreads();
        if (kc + 1 < NKC) {
            const uint32_t soff = ((kc + 1) & 1) * STAGE_B;
            const int go = (kc + 1) * 32;
#pragma unroll
            for (int t = 0; t < 2; t++) {
                CP16(sA0 + soff + t * TILE_B, gA[t] + go);
                CP16(sA1 + soff + t * TILE_B, gA[t] + (size_t)64 * HID + go);
            }
            CP_COMMIT();
        }

        const uint32_t stg = (kc & 1) * STAGE_B;
        const uint32_t aH = sb + stg + (uint32_t)(((wm * 64 + lrow) * KSTRIDE + lk) * 2);
        const uint32_t bH = sb + stg + TILE_B +
                            (uint32_t)(((wn * 32 + lrow) * KSTRIDE + lk) * 2);
#pragma unroll
        for (int ks = 0; ks < 2; ks++) {
            const uint32_t ko = (uint32_t)(ks * 32);
            uint32_t bh[4][2];
#pragma unroll
            for (int p = 0; p < 2; p++) {
                const uint32_t ba = bH + (uint32_t)(p * 16 * KSTRIDE * 2) + ko;
                uint32_t q0, q1, q2, q3;
                LDSM_X4(q0, q1, q2, q3, ba);
                bh[2 * p][0] = q0; bh[2 * p][1] = q2;
                bh[2 * p + 1][0] = q1; bh[2 * p + 1][1] = q3;
            }
#pragma unroll
            for (int mf = 0; mf < 4; mf++) {
                const uint32_t aa = aH + (uint32_t)(mf * 16 * KSTRIDE * 2) + ko;
                uint32_t a0, a1, a2, a3;
                LDSM_X4(a0, a1, a2, a3, aa);
#pragma unroll
                for (int nf = 0; nf < 4; nf++)
                    MMA_F16(acc[mf][nf][0], acc[mf][nf][1], acc[mf][nf][2], acc[mf][nf][3],
                            a0, a1, a2, a3, bh[nf][0], bh[nf][1]);
            }
        }
    }

    // ---- epilogue ----
    const int g = lane >> 2;
    const int t = lane & 3;
#pragma unroll
    for (int mf = 0; mf < 4; mf++) {
#pragma unroll
        for (int nf = 0; nf < 4; nf++) {
            const int m_lo = m0 + wm * 64 + mf * 16 + g;
            const int n    = n0 + wn * 32 + nf * 8 + t * 2;
            const float2 bb = *(const float2*)(Bias + n);
            float2 v0, v1;
            v0.x = acc[mf][nf][0] + bb.x; v0.y = acc[mf][nf][1] + bb.y;
            v1.x = acc[mf][nf][2] + bb.x; v1.y = acc[mf][nf][3] + bb.y;
            if (MODE == 0) {
                *(float2*)(OutF + (size_t)m_lo * HID + n)       = v0;
                *(float2*)(OutF + (size_t)(m_lo + 8) * HID + n) = v1;
            } else {
                v0.x *= scale; v0.y *= scale; v1.x *= scale; v1.y *= scale;
                const int h = n >> 7;
                const int d = n & (HDIM - 1);
                const int b0b = m_lo >> 11, s0 = m_lo & (SEQLEN - 1);
                const int b1b = (m_lo + 8) >> 11, s1 = (m_lo + 8) & (SEQLEN - 1);
                const size_t o0 = ((size_t)(b0b * NHEADS + h) * SEQLEN + s0) * HDIM + d;
                const size_t o1 = ((size_t)(b1b * NHEADS + h) * SEQLEN + s1) * HDIM + d;
                *(__half2*)(OutH + o0) = __floats2half2_rn(v0.x, v0.y);
                *(__half2*)(OutH + o1) = __floats2half2_rn(v1.x, v1.y);
            }
        }
    }
}

__global__ __launch_bounds__(256, 2)
void gemm_qkv_kernel(const float* __restrict__ bq, const float* __restrict__ bk,
                     const float* __restrict__ bv) {
    const int z = blockIdx.z;
    const __half* W = g_wh + (size_t)z * HID * HID;
    const float* B = (z == 0) ? bq : (z == 1 ? bk : bv);
    __half* O = (z == 0) ? g_qh : (z == 1 ? g_kh : g_vh);
    const float scale = (z == 0) ? 0.08838834764831845f : 1.0f;
    gemm_body<1>(g_xh, W, B, nullptr, O, scale);
}

__global__ __launch_bounds__(256, 2)
void gemm_out_kernel(const float* __restrict__ bo, float* __restrict__ out) {
    gemm_body<0>(g_oh, g_wh + (size_t)3 * HID * HID, bo, out, nullptr, 1.0f);
}

// ============== Flash attention (fp16, double-buffered K/V, 1 CTA/SM) ======
// EXACT R15 config (best passing): no reg cap.
#define AQ 136
#define AT_QH 0
#define AT_KV0 34816
#define KV_STG 34816
#define KV_VH  17408
#define AT_SMEM (AT_KV0 + 2 * KV_STG)    // 104448

__global__ __launch_bounds__(256, 1)
void attn_mma_kernel() {
    extern __shared__ char sm[];
    const uint32_t sb = smem_u32(sm);
    const int tid  = threadIdx.x;
    const int wid  = tid >> 5;
    const int lane = tid & 31;
    const int qt = blockIdx.x;
    const int bh = blockIdx.y;
    const int q0 = qt * 128;

    const size_t base = (size_t)bh * SEQLEN * HDIM;

    const int lrow = (lane & 7) + ((lane >> 3) & 1) * 8;
    const int lk   = (lane >> 4) * 8;
    const int g    = lane >> 2;
    const int t    = lane & 3;

    const int krow = tid >> 2;
    const int kchk = (tid & 3) * 4;
    const uint32_t kvd = sb + AT_KV0 + (uint32_t)(krow * (AQ * 2) + kchk * 16);
    const size_t   kvs = base + (size_t)krow * HDIM + kchk * 8;

    // ---- load Q tile (pure copy) ----
    {
        const int row  = tid >> 1;
        const int half = (tid & 1) * 64;
        const __half* qh = g_qh + base + (size_t)(q0 + row) * HDIM + half;
        char* dh = sm + AT_QH + (row * AQ + half) * 2;
#pragma unroll
        for (int c = 0; c < 8; c++)
            *(uint4*)(dh + c * 16) = *(const uint4*)(qh + c * 8);
    }

    // ---- prologue: prefetch KV tile 0 into stage 0 ----
#pragma unroll
    for (int c = 0; c < 4; c++) {
        CP16(kvd + c * 16,          g_kh + kvs + c * 8);
        CP16(kvd + KV_VH + c * 16,  g_vh + kvs + c * 8);
    }
    CP_COMMIT();

    float mi0 = -INFINITY, mi1 = -INFINITY, li0 = 0.f, li1 = 0.f;
    float o[16][4];
#pragma unroll
    for (int nf = 0; nf < 16; nf++)
#pragma unroll
        for (int c = 0; c < 4; c++) o[nf][c] = 0.f;

    const int qrow0 = q0 + wid * 16 + g;
    const int qrow1 = qrow0 + 8;
    const int jmax  = 2 * qt + 2;

    const uint32_t aQ  = sb + AT_QH + (uint32_t)(((wid * 16 + lrow) * AQ + lk) * 2);
    const uint32_t bK0 = sb + AT_KV0 + (uint32_t)((lrow * AQ + lk) * 2);
    const uint32_t bV0 = sb + AT_KV0 + KV_VH +
        (uint32_t)((((lane & 7) + ((lane >> 3) & 1) * 8) * AQ + ((lane >> 4) & 1) * 8) * 2);

    for (int j = 0; j < jmax; j++) {
        CP_WAIT0();
        __syncthreads();

        // ---- prefetch KV tile j+1 into alternate stage ----
        if (j + 1 < jmax) {
            const uint32_t so = ((j + 1) & 1) * KV_STG;
            const size_t  gso = kvs + (size_t)(j + 1) * 64 * HDIM;
#pragma unroll
            for (int c = 0; c < 4; c++) {
                CP16(kvd + so + c * 16,         g_kh + gso + c * 8);
                CP16(kvd + so + KV_VH + c * 16, g_vh + gso + c * 8);
            }
            CP_COMMIT();
        }

        const int k0 = j * 64;
        const uint32_t stg = (j & 1) * KV_STG;
        const uint32_t bKh = bK0 + stg;
        const uint32_t bVt = bV0 + stg;

        // ---- S = Q @ K^T ----
        float s[8][4];
#pragma unroll
        for (int nf = 0; nf < 8; nf++)
#pragma unroll
            for (int c = 0; c < 4; c++) s[nf][c] = 0.f;

#pragma unroll
        for (int ks = 0; ks < 8; ks++) {
            const uint32_t ko = (uint32_t)(ks * 32);
            uint32_t q0r, q1r, q2r, q3r;
            LDSM_X4(q0r, q1r, q2r, q3r, aQ + ko);
#pragma unroll
            for (int p = 0; p < 4; p++) {
                const uint32_t po = (uint32_t)(p * 16 * AQ * 2) + ko;
                uint32_t kh0, kh1, kh2, kh3;
                LDSM_X4(kh0, kh1, kh2, kh3, bKh + po);
                MMA_F16(s[2*p][0], s[2*p][1], s[2*p][2], s[2*p][3],
                        q0r, q1r, q2r, q3r, kh0, kh2);
                MMA_F16(s[2*p+1][0], s[2*p+1][1], s[2*p+1][2], s[2*p+1][3],
                        q0r, q1r, q2r, q3r, kh1, kh3);
            }
        }

        // ---- causal mask ----
        if (j >= 2 * qt) {
#pragma unroll
            for (int nf = 0; nf < 8; nf++) {
                const int kc = k0 + nf * 8 + t * 2;
                if (kc     > qrow0) s[nf][0] = -INFINITY;
                if (kc + 1 > qrow0) s[nf][1] = -INFINITY;
                if (kc     > qrow1) s[nf][2] = -INFINITY;
                if (kc + 1 > qrow1) s[nf][3] = -INFINITY;
            }
        }

        // ---- online softmax + pack P (fp16) ----
        float rmax0 = -INFINITY, rmax1 = -INFINITY;
#pragma unroll
        for (int nf = 0; nf < 8; nf++) {
            rmax0 = fmaxf(rmax0, fmaxf(s[nf][0], s[nf][1]));
            rmax1 = fmaxf(rmax1, fmaxf(s[nf][2], s[nf][3]));
        }
        rmax0 = fmaxf(rmax0, __shfl_xor_sync(0xffffffffu, rmax0, 1));
        rmax0 = fmaxf(rmax0, __shfl_xor_sync(0xffffffffu, rmax0, 2));
        rmax1 = fmaxf(rmax1, __shfl_xor_sync(0xffffffffu, rmax1, 1));
        rmax1 = fmaxf(rmax1, __shfl_xor_sync(0xffffffffu, rmax1, 2));
        const float mn0 = fmaxf(mi0, rmax0);
        const float mn1 = fmaxf(mi1, rmax1);
        const float corr0 = __expf(mi0 - mn0);
        const float corr1 = __expf(mi1 - mn1);
        mi0 = mn0; mi1 = mn1;

        uint32_t ph[4][4];
        float rs0 = 0.f, rs1 = 0.f;
#pragma unroll
        for (int nf = 0; nf < 8; nf++) {
            const float p0 = __expf(s[nf][0] - mn0);
            const float p1 = __expf(s[nf][1] - mn0);
            const float p2 = __expf(s[nf][2] - mn1);
            const float p3 = __expf(s[nf][3] - mn1);
            rs0 += p0 + p1;
            rs1 += p2 + p3;
            const int ks = nf >> 1;
            const int r  = (nf & 1) * 2;
            ph[ks][r]     = pack_f16(p0, p1);
            ph[ks][r + 1] = pack_f16(p2, p3);
        }
        rs0 += __shfl_xor_sync(0xffffffffu, rs0, 1);
        rs0 += __shfl_xor_sync(0xffffffffu, rs0, 2);
        rs1 += __shfl_xor_sync(0xffffffffu, rs1, 1);
        rs1 += __shfl_xor_sync(0xffffffffu, rs1, 2);
        li0 = li0 * corr0 + rs0;
        li1 = li1 * corr1 + rs1;

#pragma unroll
        for (int nf = 0; nf < 16; nf++) {
            o[nf][0] *= corr0; o[nf][1] *= corr0;
            o[nf][2] *= corr1; o[nf][3] *= corr1;
        }

        // ---- O += P @ V (V via ldmatrix.trans) ----
#pragma unroll
        for (int ks = 0; ks < 4; ks++) {
            const uint32_t kvo = (uint32_t)(ks * 16 * AQ * 2);
#pragma unroll
            for (int p = 0; p < 8; p++) {
                const uint32_t va = bVt + kvo + (uint32_t)(p * 16 * 2);
                uint32_t vh0, vh1, vh2, vh3;
                LDSM_X4_T(vh0, vh1, vh2, vh3, va);
                MMA_F16(o[2*p][0], o[2*p][1], o[2*p][2], o[2*p][3],
                        ph[ks][0], ph[ks][1], ph[ks][2], ph[ks][3], vh0, vh1);
                MMA_F16(o[2*p+1][0], o[2*p+1][1], o[2*p+1][2], o[2*p+1][3],
                        ph[ks][0], ph[ks][1], ph[ks][2], ph[ks][3], vh2, vh3);
            }
        }
    }

    // ---- normalize + write fp16 attn output ----
    const int b = bh >> 4, h = bh & 15;
    const float inv0 = 1.0f / li0;
    const float inv1 = 1.0f / li1;
    const size_t r0base = ((size_t)b * SEQLEN + qrow0) * HID + h * HDIM;
    const size_t r1base = ((size_t)b * SEQLEN + qrow1) * HID + h * HDIM;
#pragma unroll
    for (int nf = 0; nf < 16; nf++) {
        const int d = nf * 8 + t * 2;
        *(__half2*)(g_oh + r0base + d) = __floats2half2_rn(o[nf][0] * inv0, o[nf][1] * inv0);
        *(__half2*)(g_oh + r1base + d) = __floats2half2_rn(o[nf][2] * inv1, o[nf][3] * inv1);
    }
}

// ---------------------------------------------------------------------------
extern "C" void kernel_launch(void* const* d_in, const int* in_sizes, int n_in,
                              void* d_out, int out_size) {
    const float* x  = (const float*)d_in[0];
    const float* wq = (const float*)d_in[1];
    const float* wk = (const float*)d_in[2];
    const float* wv = (const float*)d_in[3];
    const float* wo = (const float*)d_in[4];
    const float* bq = (const float*)d_in[5];
    const float* bk = (const float*)d_in[6];
    const float* bv = (const float*)d_in[7];
    const float* bo = (const float*)d_in[8];
    float* out = (float*)d_out;

    cudaFuncSetAttribute(gemm_qkv_kernel,
                         cudaFuncAttributeMaxDynamicSharedMemorySize, GSM_TOTAL);
    cudaFuncSetAttribute(gemm_out_kernel,
                         cudaFuncAttributeMaxDynamicSharedMemorySize, GSM_TOTAL);
    cudaFuncSetAttribute(attn_mma_kernel,
                         cudaFuncAttributeMaxDynamicSharedMemorySize, AT_SMEM);

    // 0) fused one-time fp16 rounding (x + 4 weights)
    prep_kernel<<<dim3(MTOT * HID / 1024, 5), 256>>>(x, wq, wk, wv, wo);

    // 1) QKV projections (single-term fp16 GEMM, 2 CTAs/SM)
    gemm_qkv_kernel<<<dim3(HID / 128, MTOT / 128, 3), 256, GSM_TOTAL>>>(bq, bk, bv);
    // 2) Causal flash attention (fp16, double-buffered K/V, 1 CTA/SM)
    attn_mma_kernel<<<dim3(SEQLEN / 128, BATCHSZ * NHEADS), 256, AT_SMEM>>>();
    // 3) Output projection (2 CTAs/SM)
    gemm_out_kernel<<<dim3(HID / 128, MTOT / 128), 256, GSM_TOTAL>>>(bo, out);
}